// round 2
// baseline (speedup 1.0000x reference)
#include <cuda_runtime.h>
#include <math.h>

#define TOKENS 4096
#define DDIM   1024

// scratch: per-token scalar s[t] (no cudaMalloc allowed)
__device__ float g_s[TOKENS];

__device__ __forceinline__ float softplusf(float z) {
    // log1p(exp(z)) with overflow guard; exp underflow gives correct limit 0.
    if (z > 20.0f) return z;
    return log1pf(expf(z));
}

// ---------------------------------------------------------------------------
// Kernel 1: s[t] = sum_n (x@W2^T + b2)[t,n] * (x@W3^T + b3)[t,n]
// Block = 32 tokens, 256 threads. Thread: token = tid&31, group g = tid>>5
// owns 4 of the 32 outputs (rows 0..15 = W2/Bm, rows 16..31 = W3/Cm).
// ---------------------------------------------------------------------------
__global__ __launch_bounds__(256) void s_kernel(
    const float* __restrict__ x,
    const float* __restrict__ W2, const float* __restrict__ b2,
    const float* __restrict__ W3, const float* __restrict__ b3)
{
    __shared__ float sx[64][33];   // x tile transposed: [k][token], padded
    __shared__ float sw[32][64];   // weight tile: [n][k]
    __shared__ float sout[32][33]; // [token][n]

    const int tid = threadIdx.x;
    const int t0  = blockIdx.x * 32;
    const int tok = tid & 31;
    const int g   = tid >> 5;

    float acc[4] = {0.f, 0.f, 0.f, 0.f};

    for (int k0 = 0; k0 < DDIM; k0 += 64) {
        // load x tile (32 tokens x 64 k) transposed into sx
        {
            int f4 = tid;
            #pragma unroll
            for (int it = 0; it < 2; ++it) {
                int tk = f4 >> 4;      // token 0..31
                int c4 = f4 & 15;      // float4 column
                float4 v = *reinterpret_cast<const float4*>(
                    &x[(size_t)(t0 + tk) * DDIM + k0 + c4 * 4]);
                sx[c4 * 4 + 0][tk] = v.x;
                sx[c4 * 4 + 1][tk] = v.y;
                sx[c4 * 4 + 2][tk] = v.z;
                sx[c4 * 4 + 3][tk] = v.w;
                f4 += 256;
            }
        }
        // load weight tile: rows 0..15 from W2, rows 16..31 from W3
        {
            int f4 = tid;
            #pragma unroll
            for (int it = 0; it < 2; ++it) {
                int n  = f4 >> 4;
                int c4 = f4 & 15;
                const float* src = (n < 16) ? &W2[(size_t)n * DDIM]
                                            : &W3[(size_t)(n - 16) * DDIM];
                *reinterpret_cast<float4*>(&sw[n][c4 * 4]) =
                    *reinterpret_cast<const float4*>(&src[k0 + c4 * 4]);
                f4 += 256;
            }
        }
        __syncthreads();
        #pragma unroll 8
        for (int k = 0; k < 64; ++k) {
            float xv = sx[k][tok];
            #pragma unroll
            for (int j = 0; j < 4; ++j)
                acc[j] += xv * sw[g * 4 + j][k];
        }
        __syncthreads();
    }

    #pragma unroll
    for (int j = 0; j < 4; ++j) sout[tok][g * 4 + j] = acc[j];
    __syncthreads();

    if (tid < 32) {
        float s = 0.f;
        #pragma unroll
        for (int n = 0; n < 16; ++n)
            s += (sout[tid][n] + b2[n]) * (sout[tid][16 + n] + b3[n]);
        g_s[t0 + tid] = s;
    }
}

// ---------------------------------------------------------------------------
// Kernel 2: fused GEMM + epilogue
//   y[t,d] = x[t,d] * softplus( (x @ W1^T)[t,d] + b1[d] ) * s[t]
// 128x128 block tile, BK=8, 256 threads, 8x8 microtile (split 4+4 layout),
// register double-buffered global loads, transposed smem tiles.
// ---------------------------------------------------------------------------
#define BM 128
#define BN 128
#define BK 8

__global__ __launch_bounds__(256) void fused_gemm_kernel(
    const float* __restrict__ x,
    const float* __restrict__ W1,
    const float* __restrict__ b1,
    float* __restrict__ y)
{
    __shared__ float sA[BK][BM + 4];   // [8][132] x tile transposed
    __shared__ float sB[BK][BN + 4];   // [8][132] W1 tile transposed

    const int tid   = threadIdx.x;
    const int cx    = tid & 15;        // column group (B/N side)
    const int cy    = tid >> 4;        // row group    (A/M side)
    const int rbase = blockIdx.y * BM;
    const int cbase = blockIdx.x * BN;

    // global->smem load mapping: 256 float4 per tile per operand
    const int lrow = tid >> 1;           // 0..127
    const int lc4  = (tid & 1) * 4;      // 0 or 4

    const float* gA = &x [(size_t)(rbase + lrow) * DDIM + lc4];
    const float* gB = &W1[(size_t)(cbase + lrow) * DDIM + lc4];

    float acc[8][8];
    #pragma unroll
    for (int i = 0; i < 8; ++i)
        #pragma unroll
        for (int j = 0; j < 8; ++j)
            acc[i][j] = 0.f;

    // prologue: tile 0
    {
        float4 pa = *reinterpret_cast<const float4*>(gA);
        float4 pb = *reinterpret_cast<const float4*>(gB);
        sA[lc4 + 0][lrow] = pa.x; sA[lc4 + 1][lrow] = pa.y;
        sA[lc4 + 2][lrow] = pa.z; sA[lc4 + 3][lrow] = pa.w;
        sB[lc4 + 0][lrow] = pb.x; sB[lc4 + 1][lrow] = pb.y;
        sB[lc4 + 2][lrow] = pb.z; sB[lc4 + 3][lrow] = pb.w;
    }
    __syncthreads();

    const int NT = DDIM / BK;  // 128
    for (int t = 0; t < NT; ++t) {
        float4 na, nb;
        if (t + 1 < NT) {
            na = *reinterpret_cast<const float4*>(gA + (t + 1) * BK);
            nb = *reinterpret_cast<const float4*>(gB + (t + 1) * BK);
        }
        #pragma unroll
        for (int k = 0; k < BK; ++k) {
            float fa[8], fb[8];
            *reinterpret_cast<float4*>(&fa[0]) =
                *reinterpret_cast<const float4*>(&sA[k][cy * 4]);
            *reinterpret_cast<float4*>(&fa[4]) =
                *reinterpret_cast<const float4*>(&sA[k][64 + cy * 4]);
            *reinterpret_cast<float4*>(&fb[0]) =
                *reinterpret_cast<const float4*>(&sB[k][cx * 4]);
            *reinterpret_cast<float4*>(&fb[4]) =
                *reinterpret_cast<const float4*>(&sB[k][64 + cx * 4]);
            #pragma unroll
            for (int i = 0; i < 8; ++i)
                #pragma unroll
                for (int j = 0; j < 8; ++j)
                    acc[i][j] += fa[i] * fb[j];
        }
        __syncthreads();
        if (t + 1 < NT) {
            sA[lc4 + 0][lrow] = na.x; sA[lc4 + 1][lrow] = na.y;
            sA[lc4 + 2][lrow] = na.z; sA[lc4 + 3][lrow] = na.w;
            sB[lc4 + 0][lrow] = nb.x; sB[lc4 + 1][lrow] = nb.y;
            sB[lc4 + 2][lrow] = nb.z; sB[lc4 + 3][lrow] = nb.w;
            __syncthreads();
        }
    }

    // epilogue: y = x * softplus(acc + b1) * s
    #pragma unroll
    for (int ih = 0; ih < 2; ++ih) {
        #pragma unroll
        for (int i = 0; i < 4; ++i) {
            const int r = rbase + ih * 64 + cy * 4 + i;
            const float sv = g_s[r];
            const float* xrow = &x[(size_t)r * DDIM];
            float*       yrow = &y[(size_t)r * DDIM];
            #pragma unroll
            for (int jh = 0; jh < 2; ++jh) {
                const int c = cbase + jh * 64 + cx * 4;
                float4 xv = *reinterpret_cast<const float4*>(&xrow[c]);
                float4 bv = *reinterpret_cast<const float4*>(&b1[c]);
                float4 o;
                o.x = xv.x * softplusf(acc[ih * 4 + i][jh * 4 + 0] + bv.x) * sv;
                o.y = xv.y * softplusf(acc[ih * 4 + i][jh * 4 + 1] + bv.y) * sv;
                o.z = xv.z * softplusf(acc[ih * 4 + i][jh * 4 + 2] + bv.z) * sv;
                o.w = xv.w * softplusf(acc[ih * 4 + i][jh * 4 + 3] + bv.w) * sv;
                *reinterpret_cast<float4*>(&yrow[c]) = o;
            }
        }
    }
}

extern "C" void kernel_launch(void* const* d_in, const int* in_sizes, int n_in,
                              void* d_out, int out_size)
{
    const float* x  = (const float*)d_in[0];
    const float* W1 = (const float*)d_in[1];
    const float* b1 = (const float*)d_in[2];
    const float* W2 = (const float*)d_in[3];
    const float* b2 = (const float*)d_in[4];
    const float* W3 = (const float*)d_in[5];
    const float* b3 = (const float*)d_in[6];
    // d_in[7] = A is mathematically dead (multiplies zero-initialized h).
    float* y = (float*)d_out;

    s_kernel<<<TOKENS / 32, 256>>>(x, W2, b2, W3, b3);

    dim3 grid(DDIM / BN, TOKENS / BM);  // (8, 32) = 256 blocks
    fused_gemm_kernel<<<grid, 256>>>(x, W1, b1, y);
}

// round 4
// speedup vs baseline: 1.4863x; 1.4863x over previous
#include <cuda_runtime.h>
#include <cuda_bf16.h>
#include <math.h>
#include <stdint.h>

#define TOKENS 4096
#define DDIM   1024

// ---------------------------------------------------------------------------
// scratch (__device__ globals; no cudaMalloc allowed)
// ---------------------------------------------------------------------------
__device__ float g_s[TOKENS];
__device__ __align__(1024) __nv_bfloat16 g_xhi[TOKENS * DDIM];
__device__ __align__(1024) __nv_bfloat16 g_xlo[TOKENS * DDIM];
__device__ __align__(1024) __nv_bfloat16 g_whi[DDIM * DDIM];
__device__ __align__(1024) __nv_bfloat16 g_wlo[DDIM * DDIM];

__device__ __forceinline__ float softplusf(float z) {
    if (z > 20.0f) return z;
    return log1pf(expf(z));
}

__device__ __forceinline__ uint32_t smem_u32(const void* p) {
    uint32_t a;
    asm("{ .reg .u64 t; cvta.to.shared.u64 t, %1; cvt.u32.u64 %0, t; }"
        : "=r"(a) : "l"(p));
    return a;
}

__device__ __forceinline__ void cp16(uint32_t dst, const void* src) {
    asm volatile("cp.async.cg.shared.global [%0], [%1], 16;"
                 :: "r"(dst), "l"(src) : "memory");
}
#define CP_COMMIT() asm volatile("cp.async.commit_group;" ::: "memory")
#define CP_WAIT2()  asm volatile("cp.async.wait_group 2;" ::: "memory")

__device__ __forceinline__ void ldsm_x4(uint32_t* r, uint32_t addr) {
    asm volatile("ldmatrix.sync.aligned.m8n8.x4.shared.b16 {%0,%1,%2,%3}, [%4];"
                 : "=r"(r[0]), "=r"(r[1]), "=r"(r[2]), "=r"(r[3]) : "r"(addr));
}
__device__ __forceinline__ void ldsm_x2(uint32_t* r, uint32_t addr) {
    asm volatile("ldmatrix.sync.aligned.m8n8.x2.shared.b16 {%0,%1}, [%2];"
                 : "=r"(r[0]), "=r"(r[1]) : "r"(addr));
}
__device__ __forceinline__ void mma16816(float* d, const uint32_t* a,
                                         const uint32_t* b) {
    asm volatile(
        "mma.sync.aligned.m16n8k16.row.col.f32.bf16.bf16.f32 "
        "{%0,%1,%2,%3}, {%4,%5,%6,%7}, {%8,%9}, {%0,%1,%2,%3};"
        : "+f"(d[0]), "+f"(d[1]), "+f"(d[2]), "+f"(d[3])
        : "r"(a[0]), "r"(a[1]), "r"(a[2]), "r"(a[3]), "r"(b[0]), "r"(b[1]));
}

// ---------------------------------------------------------------------------
// Kernel 0: elementwise split of x (4M) and W1 (1M) into bf16 hi/lo.
// Each thread handles 8 floats.
// ---------------------------------------------------------------------------
#define X_CHUNKS (TOKENS * DDIM / 8)   // 524288
#define W_CHUNKS (DDIM * DDIM / 8)     // 131072
__global__ __launch_bounds__(256) void convert_kernel(
    const float* __restrict__ X, const float* __restrict__ W)
{
    int gid = blockIdx.x * 256 + threadIdx.x;
    if (gid >= X_CHUNKS + W_CHUNKS) return;
    const float* src;
    __nv_bfloat16 *dhi, *dlo;
    size_t off;
    if (gid < X_CHUNKS) {
        off = (size_t)gid * 8;
        src = X + off; dhi = g_xhi + off; dlo = g_xlo + off;
    } else {
        off = (size_t)(gid - X_CHUNKS) * 8;
        src = W + off; dhi = g_whi + off; dlo = g_wlo + off;
    }
    float4 v0 = *reinterpret_cast<const float4*>(src);
    float4 v1 = *reinterpret_cast<const float4*>(src + 4);
    float v[8] = {v0.x, v0.y, v0.z, v0.w, v1.x, v1.y, v1.z, v1.w};
    uint32_t ph[4], pl[4];
    #pragma unroll
    for (int i = 0; i < 4; ++i) {
        __nv_bfloat16 h0 = __float2bfloat16_rn(v[2 * i]);
        __nv_bfloat16 h1 = __float2bfloat16_rn(v[2 * i + 1]);
        __nv_bfloat16 l0 = __float2bfloat16_rn(v[2 * i]     - __bfloat162float(h0));
        __nv_bfloat16 l1 = __float2bfloat16_rn(v[2 * i + 1] - __bfloat162float(h1));
        ph[i] = (uint32_t)__bfloat16_as_ushort(h0) |
                ((uint32_t)__bfloat16_as_ushort(h1) << 16);
        pl[i] = (uint32_t)__bfloat16_as_ushort(l0) |
                ((uint32_t)__bfloat16_as_ushort(l1) << 16);
    }
    *reinterpret_cast<uint4*>(dhi) = make_uint4(ph[0], ph[1], ph[2], ph[3]);
    *reinterpret_cast<uint4*>(dlo) = make_uint4(pl[0], pl[1], pl[2], pl[3]);
}

// ---------------------------------------------------------------------------
// Kernel 1: s[t] = sum_n (x@W2^T + b2)[t,n] * (x@W3^T + b3)[t,n]   (fp32)
// ---------------------------------------------------------------------------
__global__ __launch_bounds__(256) void s_kernel(
    const float* __restrict__ x,
    const float* __restrict__ W2, const float* __restrict__ b2,
    const float* __restrict__ W3, const float* __restrict__ b3)
{
    __shared__ float sx[32][68];
    __shared__ float sw[32][64];
    __shared__ float sout[32][33];

    const int tid = threadIdx.x;
    const int t0  = blockIdx.x * 32;
    const int tok = tid & 31;
    const int g   = tid >> 5;

    float acc[4] = {0.f, 0.f, 0.f, 0.f};

    for (int k0 = 0; k0 < DDIM; k0 += 64) {
        for (int f4 = tid; f4 < 512; f4 += 256) {
            int tk = f4 >> 4, c4 = f4 & 15;
            *reinterpret_cast<float4*>(&sx[tk][c4 * 4]) =
                *reinterpret_cast<const float4*>(
                    &x[(size_t)(t0 + tk) * DDIM + k0 + c4 * 4]);
        }
        for (int f4 = tid; f4 < 512; f4 += 256) {
            int n = f4 >> 4, c4 = f4 & 15;
            const float* src = (n < 16) ? &W2[(size_t)n * DDIM]
                                        : &W3[(size_t)(n - 16) * DDIM];
            *reinterpret_cast<float4*>(&sw[n][c4 * 4]) =
                *reinterpret_cast<const float4*>(&src[k0 + c4 * 4]);
        }
        __syncthreads();
        #pragma unroll
        for (int k4 = 0; k4 < 16; ++k4) {
            float4 xv = *reinterpret_cast<const float4*>(&sx[tok][k4 * 4]);
            #pragma unroll
            for (int j = 0; j < 4; ++j) {
                float4 wv = *reinterpret_cast<const float4*>(&sw[g * 4 + j][k4 * 4]);
                acc[j] += xv.x * wv.x + xv.y * wv.y + xv.z * wv.z + xv.w * wv.w;
            }
        }
        __syncthreads();
    }

    #pragma unroll
    for (int j = 0; j < 4; ++j) sout[tok][g * 4 + j] = acc[j];
    __syncthreads();

    if (tid < 32) {
        float s = 0.f;
        #pragma unroll
        for (int n = 0; n < 16; ++n)
            s += (sout[tid][n] + b2[n]) * (sout[tid][16 + n] + b3[n]);
        g_s[t0 + tid] = s;
    }
}

// ---------------------------------------------------------------------------
// Kernel 2: mma.sync bf16x3 GEMM + fused epilogue
//   D = xhi@whi^T + xhi@wlo^T + xlo@whi^T  (fp32 accum)
//   y[r,c] = x[r,c] * softplus(D[r,c] + b1[c]) * s[r]
// BM=BN=128, BK=32, 4 cp.async stages, 256 threads (8 warps, 64x32 warp tile).
// ---------------------------------------------------------------------------
#define BK 32
#define NT (DDIM / BK)     // 32
#define STAGES 4
#define ROW_B 80                         // smem row pitch bytes (64B data + 16B pad)
#define PART_B (128 * ROW_B)             // 10240
#define STAGE_B (4 * PART_B)             // 40960: Ahi, Alo, Bhi, Blo
#define GEMM_SMEM (STAGES * STAGE_B)     // 163840

__device__ __forceinline__ void load_stage(uint32_t sdyn, int s, int kt,
                                           int rbase, int cbase, int tid)
{
    const int k0 = kt * BK;
    const uint32_t sb = sdyn + s * STAGE_B;
    #pragma unroll
    for (int q = 0; q < 2; ++q) {
        int idx = tid * 2 + q;
        int row = idx >> 2, c = idx & 3;
        size_t offA = (size_t)(rbase + row) * DDIM + k0 + c * 8;
        size_t offB = (size_t)(cbase + row) * DDIM + k0 + c * 8;
        uint32_t d = row * ROW_B + c * 16;
        cp16(sb + 0 * PART_B + d, g_xhi + offA);
        cp16(sb + 1 * PART_B + d, g_xlo + offA);
        cp16(sb + 2 * PART_B + d, g_whi + offB);
        cp16(sb + 3 * PART_B + d, g_wlo + offB);
    }
}

__global__ __launch_bounds__(256, 1) void gemm_kernel(
    const float* __restrict__ x,
    const float* __restrict__ b1,
    float* __restrict__ y)
{
    extern __shared__ char smem[];
    const uint32_t sdyn = smem_u32(smem);
    const int tid    = threadIdx.x;
    const int wid    = tid >> 5;
    const int lane   = tid & 31;
    const int warp_m = wid & 1;   // 0..1 -> 64 rows
    const int warp_n = wid >> 1;  // 0..3 -> 32 cols
    const int rbase  = blockIdx.y * 128;
    const int cbase  = blockIdx.x * 128;

    float acc[4][4][4];
    #pragma unroll
    for (int i = 0; i < 4; ++i)
        #pragma unroll
        for (int j = 0; j < 4; ++j)
            #pragma unroll
            for (int e = 0; e < 4; ++e)
                acc[i][j][e] = 0.f;

    // prologue: stages 0..2
    #pragma unroll
    for (int s = 0; s < STAGES - 1; ++s) {
        load_stage(sdyn, s, s, rbase, cbase, tid);
        CP_COMMIT();
    }

    // precomputed intra-part frag address offsets
    const uint32_t aoff = (uint32_t)((warp_m * 64 + (lane & 15)) * ROW_B
                                     + (lane >> 4) * 16);
    const uint32_t boff = (uint32_t)((warp_n * 32 + (lane & 7)) * ROW_B
                                     + ((lane >> 3) & 1) * 16);

    for (int kt = 0; kt < NT; ++kt) {
        CP_WAIT2();
        __syncthreads();
        if (kt + STAGES - 1 < NT)
            load_stage(sdyn, (kt + STAGES - 1) % STAGES, kt + STAGES - 1,
                       rbase, cbase, tid);
        CP_COMMIT();

        const uint32_t sb = sdyn + (kt % STAGES) * STAGE_B;
        const uint32_t ah = sb + 0 * PART_B;
        const uint32_t al = sb + 1 * PART_B;
        const uint32_t bh = sb + 2 * PART_B;
        const uint32_t bl = sb + 3 * PART_B;

        #pragma unroll
        for (int kk = 0; kk < 2; ++kk) {       // two k16 halves of BK=32
            const uint32_t kb = kk * 32;       // 16 bf16 = 32 bytes
            uint32_t Ah[4][4], Al[4][4], Bh[4][2], Bl[4][2];
            #pragma unroll
            for (int i = 0; i < 4; ++i) {
                ldsm_x4(Ah[i], ah + aoff + i * 16 * ROW_B + kb);
                ldsm_x4(Al[i], al + aoff + i * 16 * ROW_B + kb);
            }
            #pragma unroll
            for (int j = 0; j < 4; ++j) {
                ldsm_x2(Bh[j], bh + boff + j * 8 * ROW_B + kb);
                ldsm_x2(Bl[j], bl + boff + j * 8 * ROW_B + kb);
            }
            #pragma unroll
            for (int i = 0; i < 4; ++i)
                #pragma unroll
                for (int j = 0; j < 4; ++j) {
                    mma16816(acc[i][j], Ah[i], Bh[j]);
                    mma16816(acc[i][j], Ah[i], Bl[j]);
                    mma16816(acc[i][j], Al[i], Bh[j]);
                }
        }
    }

    // epilogue: y = x * softplus(acc + b1) * s
    #pragma unroll
    for (int i = 0; i < 4; ++i) {
        const int r0 = rbase + warp_m * 64 + i * 16 + (lane >> 2);
        const int r1 = r0 + 8;
        const float s0 = g_s[r0], s1 = g_s[r1];
        #pragma unroll
        for (int j = 0; j < 4; ++j) {
            const int c = cbase + warp_n * 32 + j * 8 + (lane & 3) * 2;
            float2 bv = *reinterpret_cast<const float2*>(b1 + c);
            float2 x0 = *reinterpret_cast<const float2*>(x + (size_t)r0 * DDIM + c);
            float2 x1 = *reinterpret_cast<const float2*>(x + (size_t)r1 * DDIM + c);
            float2 o0, o1;
            o0.x = x0.x * softplusf(acc[i][j][0] + bv.x) * s0;
            o0.y = x0.y * softplusf(acc[i][j][1] + bv.y) * s0;
            o1.x = x1.x * softplusf(acc[i][j][2] + bv.x) * s1;
            o1.y = x1.y * softplusf(acc[i][j][3] + bv.y) * s1;
            *reinterpret_cast<float2*>(y + (size_t)r0 * DDIM + c) = o0;
            *reinterpret_cast<float2*>(y + (size_t)r1 * DDIM + c) = o1;
        }
    }
}

// ---------------------------------------------------------------------------
extern "C" void kernel_launch(void* const* d_in, const int* in_sizes, int n_in,
                              void* d_out, int out_size)
{
    const float* x  = (const float*)d_in[0];
    const float* W1 = (const float*)d_in[1];
    const float* b1 = (const float*)d_in[2];
    const float* W2 = (const float*)d_in[3];
    const float* b2 = (const float*)d_in[4];
    const float* W3 = (const float*)d_in[5];
    const float* b3 = (const float*)d_in[6];
    // d_in[7] = A is mathematically dead (multiplies zero-initialized h).
    float* y = (float*)d_out;

    cudaFuncSetAttribute(gemm_kernel,
                         cudaFuncAttributeMaxDynamicSharedMemorySize, GEMM_SMEM);

    convert_kernel<<<(X_CHUNKS + W_CHUNKS + 255) / 256, 256>>>(x, W1);
    s_kernel<<<TOKENS / 32, 256>>>(x, W2, b2, W3, b3);

    dim3 grid(DDIM / 128, TOKENS / 128);   // (8, 32)
    gemm_kernel<<<grid, 256, GEMM_SMEM>>>(x, b1, y);
}

// round 5
// speedup vs baseline: 2.0274x; 1.3641x over previous
#include <cuda_runtime.h>
#include <cuda_bf16.h>
#include <math.h>
#include <stdint.h>

#define TOKENS 4096
#define DDIM   1024

// ---------------------------------------------------------------------------
// scratch (__device__ globals; no cudaMalloc allowed)
// x/W1 hi+lo bf16, PRE-TILED into 16KB tiles (128 rows x 64 cols, SW128-swizzled)
// x: 32 mb x 16 kt = 512 tiles;  W1: 8 nb x 16 kt = 128 tiles
// ---------------------------------------------------------------------------
__device__ float g_s[TOKENS];
__device__ __align__(1024) uint4 g_xhi[512 * 1024];
__device__ __align__(1024) uint4 g_xlo[512 * 1024];
__device__ __align__(1024) uint4 g_whi[128 * 1024];
__device__ __align__(1024) uint4 g_wlo[128 * 1024];

__device__ __forceinline__ float softplusf(float z) {
    if (z > 20.0f) return z;
    return log1pf(expf(z));
}

__device__ __forceinline__ uint32_t smem_u32(const void* p) {
    uint32_t a;
    asm("{ .reg .u64 t; cvta.to.shared.u64 t, %1; cvt.u32.u64 %0, t; }"
        : "=r"(a) : "l"(p));
    return a;
}

#define MBARRIER_INIT(addr, cnt) \
    asm volatile("mbarrier.init.shared.b64 [%0], %1;" :: "r"(addr), "r"(cnt) : "memory")
#define MBARRIER_EXPECT_TX(addr, bytes) \
    asm volatile("mbarrier.arrive.expect_tx.shared.b64 _, [%0], %1;" \
        :: "r"(addr), "r"(bytes) : "memory")
#define MBARRIER_ARRIVE(addr) \
    asm volatile("mbarrier.arrive.shared.b64 _, [%0];" :: "r"(addr) : "memory")

#define MBARRIER_WAIT_PARITY(addr, parity) do { \
    uint32_t _m = (addr); uint32_t _p = (parity); uint32_t _d; \
    asm volatile("{\n\t.reg .pred p;\n\t" \
        "mbarrier.try_wait.parity.acquire.cta.shared::cta.b64 p, [%1], %2;\n\t" \
        "selp.b32 %0, 1, 0, p;\n\t}" : "=r"(_d) : "r"(_m), "r"(_p) : "memory"); \
    if (!_d) { \
        asm volatile("{\n\t.reg .pred P1;\n\t" \
            "WL_%=:\n\t" \
            "mbarrier.try_wait.parity.acquire.cta.shared::cta.b64 P1, [%0], %1, 0x989680;\n\t" \
            "@P1 bra.uni WD_%=;\n\t" \
            "bra.uni WL_%=;\n\t" \
            "WD_%=:\n\t}" :: "r"(_m), "r"(_p) : "memory"); \
    } \
} while (0)

__device__ __forceinline__ void bulk_g2s(uint32_t dst, const void* src,
                                         uint32_t bytes, uint32_t mbar) {
    asm volatile(
        "cp.async.bulk.shared::cluster.global.mbarrier::complete_tx::bytes "
        "[%0], [%1], %2, [%3];"
        :: "r"(dst), "l"(src), "r"(bytes), "r"(mbar) : "memory");
}

__device__ __forceinline__ void ldsm_x4(uint32_t* r, uint32_t addr) {
    asm volatile("ldmatrix.sync.aligned.m8n8.x4.shared.b16 {%0,%1,%2,%3}, [%4];"
                 : "=r"(r[0]), "=r"(r[1]), "=r"(r[2]), "=r"(r[3]) : "r"(addr));
}
__device__ __forceinline__ void ldsm_x2(uint32_t* r, uint32_t addr) {
    asm volatile("ldmatrix.sync.aligned.m8n8.x2.shared.b16 {%0,%1}, [%2];"
                 : "=r"(r[0]), "=r"(r[1]) : "r"(addr));
}
__device__ __forceinline__ void mma16816(float* d, const uint32_t* a,
                                         const uint32_t* b) {
    asm volatile(
        "mma.sync.aligned.m16n8k16.row.col.f32.bf16.bf16.f32 "
        "{%0,%1,%2,%3}, {%4,%5,%6,%7}, {%8,%9}, {%0,%1,%2,%3};"
        : "+f"(d[0]), "+f"(d[1]), "+f"(d[2]), "+f"(d[3])
        : "r"(a[0]), "r"(a[1]), "r"(a[2]), "r"(a[3]), "r"(b[0]), "r"(b[1]));
}

// ---------------------------------------------------------------------------
// Kernel 0: split into bf16 hi/lo, pre-tiled 128x64 + SW128-pre-swizzled.
// blocks 0..511: x tiles (mb = b>>4, kt = b&15); 512..639: W tiles (nb, kt).
// ---------------------------------------------------------------------------
__global__ __launch_bounds__(256) void convert_kernel(
    const float* __restrict__ X, const float* __restrict__ W)
{
    const int bid = blockIdx.x;
    const float* src;
    uint4 *dhi, *dlo;
    if (bid < 512) {
        int mb = bid >> 4, kb = bid & 15;
        src = X + (size_t)mb * 128 * DDIM + kb * 64;
        dhi = g_xhi + (size_t)bid * 1024;
        dlo = g_xlo + (size_t)bid * 1024;
    } else {
        int t = bid - 512;
        int nb = t >> 4, kb = t & 15;
        src = W + (size_t)nb * 128 * DDIM + kb * 64;
        dhi = g_whi + (size_t)t * 1024;
        dlo = g_wlo + (size_t)t * 1024;
    }
    // 1024 chunks of 8 floats per tile; 256 threads x 4
    #pragma unroll
    for (int it = 0; it < 4; ++it) {
        int c = threadIdx.x + it * 256;
        int row = c >> 3, c8 = c & 7;
        const float* p = src + (size_t)row * DDIM + c8 * 8;
        float4 v0 = *reinterpret_cast<const float4*>(p);
        float4 v1 = *reinterpret_cast<const float4*>(p + 4);
        float v[8] = {v0.x, v0.y, v0.z, v0.w, v1.x, v1.y, v1.z, v1.w};
        uint32_t ph[4], pl[4];
        #pragma unroll
        for (int i = 0; i < 4; ++i) {
            __nv_bfloat16 h0 = __float2bfloat16_rn(v[2 * i]);
            __nv_bfloat16 h1 = __float2bfloat16_rn(v[2 * i + 1]);
            __nv_bfloat16 l0 = __float2bfloat16_rn(v[2 * i]     - __bfloat162float(h0));
            __nv_bfloat16 l1 = __float2bfloat16_rn(v[2 * i + 1] - __bfloat162float(h1));
            ph[i] = (uint32_t)__bfloat16_as_ushort(h0) |
                    ((uint32_t)__bfloat16_as_ushort(h1) << 16);
            pl[i] = (uint32_t)__bfloat16_as_ushort(l0) |
                    ((uint32_t)__bfloat16_as_ushort(l1) << 16);
        }
        uint32_t off = (uint32_t)(row * 128 + c8 * 16);
        off ^= ((off >> 3) & 0x70);   // SW128 swizzle, pre-applied
        dhi[off >> 4] = make_uint4(ph[0], ph[1], ph[2], ph[3]);
        dlo[off >> 4] = make_uint4(pl[0], pl[1], pl[2], pl[3]);
    }
}

// ---------------------------------------------------------------------------
// Kernel 1: s[t] = sum_n (x@W2^T + b2)[t,n] * (x@W3^T + b3)[t,n]   (fp32)
// ---------------------------------------------------------------------------
__global__ __launch_bounds__(256) void s_kernel(
    const float* __restrict__ x,
    const float* __restrict__ W2, const float* __restrict__ b2,
    const float* __restrict__ W3, const float* __restrict__ b3)
{
    __shared__ float sx[32][68];
    __shared__ float sw[32][64];
    __shared__ float sout[32][33];

    const int tid = threadIdx.x;
    const int t0  = blockIdx.x * 32;
    const int tok = tid & 31;
    const int g   = tid >> 5;

    float acc[4] = {0.f, 0.f, 0.f, 0.f};

    for (int k0 = 0; k0 < DDIM; k0 += 64) {
        for (int f4 = tid; f4 < 512; f4 += 256) {
            int tk = f4 >> 4, c4 = f4 & 15;
            *reinterpret_cast<float4*>(&sx[tk][c4 * 4]) =
                *reinterpret_cast<const float4*>(
                    &x[(size_t)(t0 + tk) * DDIM + k0 + c4 * 4]);
        }
        for (int f4 = tid; f4 < 512; f4 += 256) {
            int n = f4 >> 4, c4 = f4 & 15;
            const float* src = (n < 16) ? &W2[(size_t)n * DDIM]
                                        : &W3[(size_t)(n - 16) * DDIM];
            *reinterpret_cast<float4*>(&sw[n][c4 * 4]) =
                *reinterpret_cast<const float4*>(&src[k0 + c4 * 4]);
        }
        __syncthreads();
        #pragma unroll
        for (int k4 = 0; k4 < 16; ++k4) {
            float4 xv = *reinterpret_cast<const float4*>(&sx[tok][k4 * 4]);
            #pragma unroll
            for (int j = 0; j < 4; ++j) {
                float4 wv = *reinterpret_cast<const float4*>(&sw[g * 4 + j][k4 * 4]);
                acc[j] += xv.x * wv.x + xv.y * wv.y + xv.z * wv.z + xv.w * wv.w;
            }
        }
        __syncthreads();
    }

    #pragma unroll
    for (int j = 0; j < 4; ++j) sout[tok][g * 4 + j] = acc[j];
    __syncthreads();

    if (tid < 32) {
        float s = 0.f;
        #pragma unroll
        for (int n = 0; n < 16; ++n)
            s += (sout[tid][n] + b2[n]) * (sout[tid][16 + n] + b3[n]);
        g_s[t0 + tid] = s;
    }
}

// ---------------------------------------------------------------------------
// Kernel 2: mma.sync bf16x3 GEMM, cp.async.bulk-fed, fused epilogue.
//   D = xhi@whi^T + xhi@wlo^T + xlo@whi^T; y = x * softplus(D + b1) * s
// BM=BN=128, BK=64, 3-stage bulk pipeline, 288 threads:
//   warps 0-7 compute (64x32 tiles), warp 8 = producer.
// ---------------------------------------------------------------------------
#define NKT 16                    // 1024 / 64
#define STAGES 3
#define PART_B 16384              // one 128x64 bf16 tile
#define STAGE_B (4 * PART_B)      // Ahi, Alo, Bhi, Blo = 64KB
#define GEMM_SMEM (STAGES * STAGE_B)   // 196608

__global__ __launch_bounds__(288, 1) void gemm_kernel(
    const float* __restrict__ x,
    const float* __restrict__ b1,
    float* __restrict__ y)
{
    extern __shared__ __align__(1024) char smem[];
    __shared__ __align__(8) uint64_t mbar[2 * STAGES];  // full[0..2], empty[0..2]

    const uint32_t sdyn = smem_u32(smem);
    const uint32_t sFull  = smem_u32(&mbar[0]);
    const uint32_t sEmpty = smem_u32(&mbar[STAGES]);

    const int tid  = threadIdx.x;
    const int wid  = tid >> 5;
    const int lane = tid & 31;
    const int nb = blockIdx.x;          // 0..7
    const int mb = blockIdx.y;          // 0..31
    const int rbase = mb * 128;
    const int cbase = nb * 128;

    if (tid == 0) {
        #pragma unroll
        for (int s = 0; s < STAGES; ++s) {
            MBARRIER_INIT(sFull  + s * 8, 1);
            MBARRIER_INIT(sEmpty + s * 8, 8);
        }
    }
    __syncthreads();

    if (wid == 8) {
        // ---------------- producer ----------------
        if (lane == 0) {
            const char* xhiB = (const char*)g_xhi;
            const char* xloB = (const char*)g_xlo;
            const char* whiB = (const char*)g_whi;
            const char* wloB = (const char*)g_wlo;
            int st = 0, ph = 1;
            for (int kt = 0; kt < NKT; ++kt) {
                MBARRIER_WAIT_PARITY(sEmpty + st * 8, ph);
                uint32_t fb = sFull + st * 8;
                MBARRIER_EXPECT_TX(fb, STAGE_B);
                uint32_t sb = sdyn + st * STAGE_B;
                size_t ax = ((size_t)(mb * NKT + kt)) * PART_B;
                size_t bw = ((size_t)(nb * NKT + kt)) * PART_B;
                bulk_g2s(sb + 0 * PART_B, xhiB + ax, PART_B, fb);
                bulk_g2s(sb + 1 * PART_B, xloB + ax, PART_B, fb);
                bulk_g2s(sb + 2 * PART_B, whiB + bw, PART_B, fb);
                bulk_g2s(sb + 3 * PART_B, wloB + bw, PART_B, fb);
                if (++st == STAGES) { st = 0; ph ^= 1; }
            }
        }
        return;
    }

    // ---------------- consumers (warps 0-7) ----------------
    const int warp_m = wid & 1;
    const int warp_n = wid >> 1;

    float acc[4][4][4];
    #pragma unroll
    for (int i = 0; i < 4; ++i)
        #pragma unroll
        for (int j = 0; j < 4; ++j)
            #pragma unroll
            for (int e = 0; e < 4; ++e)
                acc[i][j][e] = 0.f;

    // per-thread frag row bases + swizzle keys
    uint32_t aRow[4], aSw[4], bRow[4], bSw[4];
    #pragma unroll
    for (int i = 0; i < 4; ++i) {
        int r = warp_m * 64 + i * 16 + (lane & 15);
        aRow[i] = (uint32_t)r * 128;
        aSw[i]  = (uint32_t)(r & 7);
    }
    #pragma unroll
    for (int j = 0; j < 4; ++j) {
        int r = warp_n * 32 + j * 8 + (lane & 7);
        bRow[j] = (uint32_t)r * 128;
        bSw[j]  = (uint32_t)(r & 7);
    }
    const uint32_t ac0 = (uint32_t)(lane >> 4);        // 0/1
    const uint32_t bc0 = (uint32_t)((lane >> 3) & 1);  // 0/1

    int st = 0, ph = 0;
    for (int kt = 0; kt < NKT; ++kt) {
        MBARRIER_WAIT_PARITY(sFull + st * 8, ph);
        const uint32_t sb = sdyn + st * STAGE_B;
        const uint32_t ah = sb + 0 * PART_B;
        const uint32_t al = sb + 1 * PART_B;
        const uint32_t bh = sb + 2 * PART_B;
        const uint32_t bl = sb + 3 * PART_B;

        #pragma unroll
        for (int kk = 0; kk < 4; ++kk) {       // four k16 steps of BK=64
            uint32_t Ah[4][4], Al[4][4], Bh[4][2], Bl[4][2];
            const uint32_t ca = kk * 2 + ac0;
            const uint32_t cb = kk * 2 + bc0;
            #pragma unroll
            for (int i = 0; i < 4; ++i) {
                uint32_t off = aRow[i] + ((ca ^ aSw[i]) << 4);
                ldsm_x4(Ah[i], ah + off);
                ldsm_x4(Al[i], al + off);
            }
            #pragma unroll
            for (int j = 0; j < 4; ++j) {
                uint32_t off = bRow[j] + ((cb ^ bSw[j]) << 4);
                ldsm_x2(Bh[j], bh + off);
                ldsm_x2(Bl[j], bl + off);
            }
            #pragma unroll
            for (int i = 0; i < 4; ++i)
                #pragma unroll
                for (int j = 0; j < 4; ++j) {
                    mma16816(acc[i][j], Ah[i], Bh[j]);
                    mma16816(acc[i][j], Ah[i], Bl[j]);
                    mma16816(acc[i][j], Al[i], Bh[j]);
                }
        }
        if (lane == 0) MBARRIER_ARRIVE(sEmpty + st * 8);
        if (++st == STAGES) { st = 0; ph ^= 1; }
    }

    // epilogue: y = x * softplus(acc + b1) * s
    #pragma unroll
    for (int i = 0; i < 4; ++i) {
        const int r0 = rbase + warp_m * 64 + i * 16 + (lane >> 2);
        const int r1 = r0 + 8;
        const float s0 = g_s[r0], s1 = g_s[r1];
        #pragma unroll
        for (int j = 0; j < 4; ++j) {
            const int c = cbase + warp_n * 32 + j * 8 + (lane & 3) * 2;
            float2 bv = *reinterpret_cast<const float2*>(b1 + c);
            float2 x0 = *reinterpret_cast<const float2*>(x + (size_t)r0 * DDIM + c);
            float2 x1 = *reinterpret_cast<const float2*>(x + (size_t)r1 * DDIM + c);
            float2 o0, o1;
            o0.x = x0.x * softplusf(acc[i][j][0] + bv.x) * s0;
            o0.y = x0.y * softplusf(acc[i][j][1] + bv.y) * s0;
            o1.x = x1.x * softplusf(acc[i][j][2] + bv.x) * s1;
            o1.y = x1.y * softplusf(acc[i][j][3] + bv.y) * s1;
            *reinterpret_cast<float2*>(y + (size_t)r0 * DDIM + c) = o0;
            *reinterpret_cast<float2*>(y + (size_t)r1 * DDIM + c) = o1;
        }
    }
}

// ---------------------------------------------------------------------------
extern "C" void kernel_launch(void* const* d_in, const int* in_sizes, int n_in,
                              void* d_out, int out_size)
{
    const float* x  = (const float*)d_in[0];
    const float* W1 = (const float*)d_in[1];
    const float* b1 = (const float*)d_in[2];
    const float* W2 = (const float*)d_in[3];
    const float* b2 = (const float*)d_in[4];
    const float* W3 = (const float*)d_in[5];
    const float* b3 = (const float*)d_in[6];
    // d_in[7] = A is mathematically dead (multiplies zero-initialized h).
    float* y = (float*)d_out;

    cudaFuncSetAttribute(gemm_kernel,
                         cudaFuncAttributeMaxDynamicSharedMemorySize, GEMM_SMEM);

    convert_kernel<<<640, 256>>>(x, W1);
    s_kernel<<<TOKENS / 32, 256>>>(x, W2, b2, W3, b3);

    dim3 grid(DDIM / 128, TOKENS / 128);   // (8, 32)
    gemm_kernel<<<grid, 288, GEMM_SMEM>>>(x, b1, y);
}